// round 15
// baseline (speedup 1.0000x reference)
#include <cuda_runtime.h>
#include <cuda_fp16.h>
#include <math.h>
#include <stdint.h>

#define BB   2
#define TT   2048
#define EE   1024
#define HQn  16
#define HKVn 4
#define DD   64
#define GG   4

#define ROWS (BB*TT)
#define KVW  (HKVn*DD)
#define Y_ELEMS  ((size_t)BB*TT*EE)
#define ATT_ELEMS ((size_t)BB*HQn*TT*TT)
#define ZHEADS (BB*HQn)
#define NQB    (TT/128)

typedef __half h16;

// ---------------- device scratch ----------------
__device__ float g_Q[ROWS * EE];
__device__ float g_K[ROWS * KVW];
__device__ float g_V[ROWS * KVW];
__device__ float g_Att[ATT_ELEMS];
__device__ float g_PS[ZHEADS * NQB * TT];

__device__ h16 g_xh[ROWS * EE],  g_xl[ROWS * EE];
__device__ h16 g_Qh[ROWS * EE];
__device__ h16 g_Kh[ROWS * KVW];
__device__ h16 g_Vth[BB * KVW * TT];
__device__ h16 g_Yh[ROWS * EE],  g_Yl[ROWS * EE];
__device__ h16 g_Wqth[EE * EE];
__device__ h16 g_Wkth[EE * KVW];
__device__ h16 g_Wvth[EE * KVW];
__device__ h16 g_Woth[EE * EE];

// ---------------- helpers ----------------
__device__ __forceinline__ void hsplit(float x, h16& h, h16& l)
{
    h = __float2half_rn(x);
    l = __float2half_rn(x - __half2float(h));
}

__device__ __forceinline__ void mma_f16(float (&c)[4],
                                        uint32_t a0, uint32_t a1,
                                        uint32_t a2, uint32_t a3,
                                        uint32_t b0, uint32_t b1)
{
    asm volatile(
        "mma.sync.aligned.m16n8k16.row.col.f32.f16.f16.f32 "
        "{%0,%1,%2,%3}, {%4,%5,%6,%7}, {%8,%9}, {%0,%1,%2,%3};"
        : "+f"(c[0]), "+f"(c[1]), "+f"(c[2]), "+f"(c[3])
        : "r"(a0), "r"(a1), "r"(a2), "r"(a3), "r"(b0), "r"(b1));
}

__device__ __forceinline__ uint32_t smem_u32(const void* p)
{
    return (uint32_t)__cvta_generic_to_shared(p);
}

__device__ __forceinline__ void cp16(uint32_t dst, const void* src)
{
    asm volatile("cp.async.cg.shared.global [%0], [%1], 16;" :: "r"(dst), "l"(src));
}
#define CP_COMMIT() asm volatile("cp.async.commit_group;")
#define CP_WAIT2()  asm volatile("cp.async.wait_group 2;")

__device__ __forceinline__ void ldsm_x4(uint32_t& r0, uint32_t& r1,
                                        uint32_t& r2, uint32_t& r3, uint32_t a)
{
    asm volatile("ldmatrix.sync.aligned.m8n8.x4.shared.b16 {%0,%1,%2,%3}, [%4];"
        : "=r"(r0), "=r"(r1), "=r"(r2), "=r"(r3) : "r"(a));
}

// ---------------- preprocessing ----------------
__global__ __launch_bounds__(256) void wtrans_all(
    const float* __restrict__ Wq, const float* __restrict__ Wk,
    const float* __restrict__ Wv, const float* __restrict__ Wo,
    h16* __restrict__ Dq, h16* __restrict__ Dk,
    h16* __restrict__ Dv, h16* __restrict__ Do)
{
    const int z = blockIdx.z;
    const float* W; h16* D; int N;
    if      (z == 0) { W = Wq; D = Dq; N = EE;  }
    else if (z == 1) { W = Wk; D = Dk; N = KVW; }
    else if (z == 2) { W = Wv; D = Dv; N = KVW; }
    else             { W = Wo; D = Do; N = EE;  }
    const int c0 = blockIdx.x * 32;
    if (c0 >= N) return;
    const int r0 = blockIdx.y * 32;

    __shared__ float s[32][33];
    const int tx = threadIdx.x, ty = threadIdx.y;
    for (int i = ty; i < 32; i += 8)
        s[i][tx] = W[(size_t)(r0 + i) * N + c0 + tx];
    __syncthreads();
    for (int i = ty; i < 32; i += 8)
        D[(size_t)(c0 + i) * EE + r0 + tx] = __float2half_rn(s[tx][i]);
}

__global__ __launch_bounds__(256) void vtrans_half(
    const float* __restrict__ V, h16* __restrict__ Vth)
{
    __shared__ float s[32][33];
    const int c0 = blockIdx.x * 32;
    const int r0 = blockIdx.y * 32;
    const int b  = r0 >> 11;
    const int t0 = r0 & 2047;
    const int tx = threadIdx.x, ty = threadIdx.y;
    for (int i = ty; i < 32; i += 8)
        s[i][tx] = V[(size_t)(r0 + i) * KVW + c0 + tx];
    __syncthreads();
    for (int i = ty; i < 32; i += 8)
        Vth[(size_t)(b * KVW + c0 + i) * TT + t0 + tx] = __float2half_rn(s[tx][i]);
}

__global__ __launch_bounds__(256) void split_x(
    const float4* __restrict__ src, h16* __restrict__ hi, h16* __restrict__ lo, int n4)
{
    int i = blockIdx.x * 256 + threadIdx.x;
    if (i >= n4) return;
    float4 v = src[i];
    h16 hx, lx, hy, ly, hz, lz, hw, lw;
    hsplit(v.x, hx, lx); hsplit(v.y, hy, ly);
    hsplit(v.z, hz, lz); hsplit(v.w, hw, lw);
    __half2 a, b2;
    a.x = hx; a.y = hy; b2.x = hz; b2.y = hw;
    ((__half2*)hi)[2 * i] = a; ((__half2*)hi)[2 * i + 1] = b2;
    a.x = lx; a.y = ly; b2.x = lz; b2.y = lw;
    ((__half2*)lo)[2 * i] = a; ((__half2*)lo)[2 * i + 1] = b2;
}

// -------- GEMM 2-pass fp16: 4-stage cp.async pipeline + ldmatrix ----------
#define BKG    32
#define PITCH  40
#define NSTAGE 4

__device__ __forceinline__ void gemm2p_body(
    const h16* __restrict__ Ah, const h16* __restrict__ Al,
    const h16* __restrict__ Bth, const float* __restrict__ bias,
    float* __restrict__ C, int blkM, int blkN, int N, int K)
{
    extern __shared__ h16 smp[];
    h16* sAh = smp;
    h16* sAl = smp + NSTAGE * 128 * PITCH;
    h16* sBh = smp + 2 * NSTAGE * 128 * PITCH;
    const uint32_t stStride = 128 * PITCH * 2;  // bytes per stage

    const int tid  = threadIdx.x;
    const int w    = tid >> 5, lane = tid & 31;
    const int m0   = (w & 1) * 64;
    const int n0   = (w >> 1) * 32;

    const int lr = tid >> 2;
    const int lk = (tid & 3) * 8;
    const h16* gAh = Ah  + (size_t)(blkM + lr) * K + lk;
    const h16* gAl = Al  + (size_t)(blkM + lr) * K + lk;
    const h16* gB  = Bth + (size_t)(blkN + lr) * K + lk;

    const uint32_t dAh0 = smem_u32(sAh) + (lr * PITCH + lk) * 2;
    const uint32_t dAh1 = smem_u32(sAh) + ((lr + 64) * PITCH + lk) * 2;
    const uint32_t dAl0 = smem_u32(sAl) + (lr * PITCH + lk) * 2;
    const uint32_t dAl1 = smem_u32(sAl) + ((lr + 64) * PITCH + lk) * 2;
    const uint32_t dB0  = smem_u32(sBh) + (lr * PITCH + lk) * 2;
    const uint32_t dB1  = smem_u32(sBh) + ((lr + 64) * PITCH + lk) * 2;

    const uint32_t offA = ((lane & 15) * PITCH + (lane >> 4) * 8) * 2;
    const uint32_t offB = ((((lane >> 4) * 8) + (lane & 7)) * PITCH + ((lane >> 3) & 1) * 8) * 2;
    const uint32_t aAh = smem_u32(sAh) + offA;
    const uint32_t aAl = smem_u32(sAl) + offA;
    const uint32_t aB  = smem_u32(sBh) + offB;

    float acc[4][4][4];
#pragma unroll
    for (int i = 0; i < 4; i++)
#pragma unroll
        for (int j = 0; j < 4; j++)
#pragma unroll
            for (int v = 0; v < 4; v++) acc[i][j][v] = 0.f;

    const int niter = K / BKG;   // 32 for K=1024

    // prologue: stages 0..2 in flight (3 groups)
#pragma unroll
    for (int s = 0; s < NSTAGE - 1; s++) {
        const int k0 = s * BKG;
        const uint32_t so = s * stStride;
        if (s < niter) {
            cp16(dAh0 + so, gAh + k0); cp16(dAh1 + so, gAh + (size_t)64 * K + k0);
            cp16(dAl0 + so, gAl + k0); cp16(dAl1 + so, gAl + (size_t)64 * K + k0);
            cp16(dB0 + so,  gB + k0);  cp16(dB1 + so,  gB  + (size_t)64 * K + k0);
        }
        CP_COMMIT();
    }

    for (int it = 0; it < niter; it++) {
        CP_WAIT2();           // oldest group (stage it) complete; ≤2 pending
        __syncthreads();      // all warps past previous compute; slot (it-1)%4 free

        // issue stage it+3 into slot (it+3)%NSTAGE == (it-1)%NSTAGE
        if (it + NSTAGE - 1 < niter) {
            const int k0 = (it + NSTAGE - 1) * BKG;
            const uint32_t so = ((it + NSTAGE - 1) & (NSTAGE - 1)) * stStride;
            cp16(dAh0 + so, gAh + k0); cp16(dAh1 + so, gAh + (size_t)64 * K + k0);
            cp16(dAl0 + so, gAl + k0); cp16(dAl1 + so, gAl + (size_t)64 * K + k0);
            cp16(dB0 + so,  gB + k0);  cp16(dB1 + so,  gB  + (size_t)64 * K + k0);
        }
        CP_COMMIT();

        const uint32_t so = (it & (NSTAGE - 1)) * stStride;
#pragma unroll
        for (int kk = 0; kk < BKG; kk += 16) {
            uint32_t ah[4][4], al[4][4], bh[4][2];
#pragma unroll
            for (int mt = 0; mt < 4; mt++) {
                const uint32_t rowoff = ((m0 + mt * 16) * PITCH + kk) * 2;
                ldsm_x4(ah[mt][0], ah[mt][1], ah[mt][2], ah[mt][3], aAh + so + rowoff);
                ldsm_x4(al[mt][0], al[mt][1], al[mt][2], al[mt][3], aAl + so + rowoff);
            }
            ldsm_x4(bh[0][0], bh[0][1], bh[1][0], bh[1][1],
                    aB + so + ((n0)      * PITCH + kk) * 2);
            ldsm_x4(bh[2][0], bh[2][1], bh[3][0], bh[3][1],
                    aB + so + ((n0 + 16) * PITCH + kk) * 2);
#pragma unroll
            for (int mt = 0; mt < 4; mt++)
#pragma unroll
                for (int nt = 0; nt < 4; nt++) {
                    mma_f16(acc[mt][nt], ah[mt][0], ah[mt][1], ah[mt][2], ah[mt][3],
                            bh[nt][0], bh[nt][1]);
                    mma_f16(acc[mt][nt], al[mt][0], al[mt][1], al[mt][2], al[mt][3],
                            bh[nt][0], bh[nt][1]);
                }
        }
    }
    __syncthreads();

    const int lg = lane >> 2, tg = lane & 3;
#pragma unroll
    for (int mt = 0; mt < 4; mt++)
#pragma unroll
        for (int nt = 0; nt < 4; nt++) {
            const int col = blkN + n0 + nt * 8 + 2 * tg;
            const float b0 = bias[col], b1 = bias[col + 1];
            const int r0 = blkM + m0 + mt * 16 + lg;
            float2 o;
            o.x = acc[mt][nt][0] + b0; o.y = acc[mt][nt][1] + b1;
            *(float2*)(C + (size_t)r0 * N + col) = o;
            o.x = acc[mt][nt][2] + b0; o.y = acc[mt][nt][3] + b1;
            *(float2*)(C + (size_t)(r0 + 8) * N + col) = o;
        }
}

__global__ __launch_bounds__(256) void gemm2p(
    const h16* __restrict__ Ah, const h16* __restrict__ Al,
    const h16* __restrict__ Bth, const float* __restrict__ bias,
    float* __restrict__ C, int N, int K)
{
    gemm2p_body(Ah, Al, Bth, bias, C, blockIdx.y * 128, blockIdx.x * 128, N, K);
}

__global__ __launch_bounds__(256) void gemm2p_qkv(
    const h16* __restrict__ Ah, const h16* __restrict__ Al,
    const h16* __restrict__ Wqth, const float* __restrict__ bq, float* __restrict__ Qout,
    const h16* __restrict__ Wkth, const float* __restrict__ bk, float* __restrict__ Kout,
    const h16* __restrict__ Wvth, const float* __restrict__ bv, float* __restrict__ Vout)
{
    const int blkM = blockIdx.y * 128;
    if (blockIdx.z == 0) {
        gemm2p_body(Ah, Al, Wqth, bq, Qout, blkM, blockIdx.x * 128, EE, EE);
    } else {
        const int x = blockIdx.x;
        if (x < 2)      gemm2p_body(Ah, Al, Wkth, bk, Kout, blkM, x * 128, KVW, EE);
        else if (x < 4) gemm2p_body(Ah, Al, Wvth, bv, Vout, blkM, (x - 2) * 128, KVW, EE);
    }
}

// ---------------- RoPE (hi only) ----------------
__global__ __launch_bounds__(256) void rope_half(
    const float* __restrict__ buf, h16* __restrict__ hi, int nheads)
{
    int idx = blockIdx.x * 256 + threadIdx.x;
    int ii  = idx & 31;
    int h   = (idx >> 5) % nheads;
    int row = idx / (32 * nheads);
    int t   = row & (TT - 1);
    float ang = (float)(t + 1) * exp2f((float)ii * (-13.2877123795494f / 32.0f));
    float sn, cs;
    sincosf(ang, &sn, &cs);
    size_t off = (size_t)row * (nheads * 64) + h * 64 + ii;
    float x0 = buf[off], x1 = buf[off + 32];
    hi[off]      = __float2half_rn(x0 * cs - x1 * sn);
    hi[off + 32] = __float2half_rn(x1 * cs + x0 * sn);
}

// -------- scores: P~ = exp(Qh·Kh^T/8), single-pass fp16 -------------------
__global__ __launch_bounds__(256) void attn_scores_exp(
    const h16* __restrict__ Qh, const h16* __restrict__ Kh,
    float* __restrict__ att, float* __restrict__ PS)
{
    int idx = blockIdx.x;
    int qb = (int)((sqrtf(8.f * idx + 1.f) - 1.f) * 0.5f);
    while ((qb + 1) * (qb + 2) / 2 <= idx) qb++;
    while (qb * (qb + 1) / 2 > idx) qb--;
    const int kb = idx - qb * (qb + 1) / 2;

    const int z   = blockIdx.y;
    const int b   = z >> 4;
    const int g   = (z >> 2) & 3;
    const int hkv = z & 3;
    const int hq  = hkv * GG + g;

    extern __shared__ h16 sm[];
    h16 (*sQh)[72] = (h16(*)[72])sm;
    h16 (*sKh)[72] = (h16(*)[72])(sm + 128 * 72);

    const int tid  = threadIdx.x;
    const int w    = tid >> 5, lane = tid & 31;
    const int lg   = lane >> 2, tg = lane & 3;
    const int m0   = (w & 1) * 64;
    const int n0   = (w >> 1) * 32;

    {
        const int lrow = tid >> 1;
        const int lc   = (tid & 1) * 32;
        const h16* qh = Qh + (size_t)(b * TT + qb * 128 + lrow) * EE + hq * 64 + lc;
        const h16* kh = Kh + (size_t)(b * TT + kb * 128 + lrow) * KVW + hkv * 64 + lc;
#pragma unroll
        for (int v = 0; v < 4; v++) {
            *(uint4*)&sQh[lrow][lc + v * 8] = *(const uint4*)(qh + v * 8);
            *(uint4*)&sKh[lrow][lc + v * 8] = *(const uint4*)(kh + v * 8);
        }
    }
    __syncthreads();

    float acc[4][4][4];
#pragma unroll
    for (int i = 0; i < 4; i++)
#pragma unroll
        for (int j = 0; j < 4; j++)
#pragma unroll
            for (int v = 0; v < 4; v++) acc[i][j][v] = 0.f;

#pragma unroll
    for (int kk = 0; kk < 64; kk += 16) {
        uint32_t ah[4][4], bh[4][2];
#pragma unroll
        for (int mt = 0; mt < 4; mt++) {
            const int r = m0 + mt * 16 + lg;
            ah[mt][0] = *(const uint32_t*)&sQh[r][kk + tg * 2];
            ah[mt][1] = *(const uint32_t*)&sQh[r + 8][kk + tg * 2];
            ah[mt][2] = *(const uint32_t*)&sQh[r][kk + tg * 2 + 8];
            ah[mt][3] = *(const uint32_t*)&sQh[r + 8][kk + tg * 2 + 8];
        }
#pragma unroll
        for (int nt = 0; nt < 4; nt++) {
            const int n = n0 + nt * 8 + lg;
            bh[nt][0] = *(const uint32_t*)&sKh[n][kk + tg * 2];
            bh[nt][1] = *(const uint32_t*)&sKh[n][kk + tg * 2 + 8];
        }
#pragma unroll
        for (int mt = 0; mt < 4; mt++)
#pragma unroll
            for (int nt = 0; nt < 4; nt++)
                mma_f16(acc[mt][nt], ah[mt][0], ah[mt][1], ah[mt][2], ah[mt][3],
                        bh[nt][0], bh[nt][1]);
    }

    __syncthreads();
    float* srow = (float*)sm;
    if (tid < 128) srow[tid] = 0.f;
    __syncthreads();

    float* obase = att + ((size_t)z * TT + qb * 128) * TT + kb * 128;
    const bool diag = (kb == qb);

#pragma unroll
    for (int mt = 0; mt < 4; mt++) {
        const int r0 = m0 + mt * 16 + lg;
        float s0 = 0.f, s1 = 0.f;
#pragma unroll
        for (int nt = 0; nt < 4; nt++) {
            const int col = n0 + nt * 8 + 2 * tg;
            float p0 = __expf(acc[mt][nt][0] * 0.125f);
            float p1 = __expf(acc[mt][nt][1] * 0.125f);
            float p2 = __expf(acc[mt][nt][2] * 0.125f);
            float p3 = __expf(acc[mt][nt][3] * 0.125f);
            if (diag) {
                if (col > r0)         p0 = 0.f;
                if (col + 1 > r0)     p1 = 0.f;
                if (col > r0 + 8)     p2 = 0.f;
                if (col + 1 > r0 + 8) p3 = 0.f;
            }
            s0 += p0 + p1;
            s1 += p2 + p3;
            float2 o;
            o.x = p0; o.y = p1;
            *(float2*)(obase + (size_t)r0 * TT + col) = o;
            o.x = p2; o.y = p3;
            *(float2*)(obase + (size_t)(r0 + 8) * TT + col) = o;
        }
        s0 += __shfl_xor_sync(0xffffffffu, s0, 1);
        s0 += __shfl_xor_sync(0xffffffffu, s0, 2);
        s1 += __shfl_xor_sync(0xffffffffu, s1, 1);
        s1 += __shfl_xor_sync(0xffffffffu, s1, 2);
        if (tg == 0) {
            atomicAdd(&srow[r0], s0);
            atomicAdd(&srow[r0 + 8], s1);
        }
    }
    __syncthreads();
    if (tid < 128)
        PS[((size_t)z * NQB + kb) * TT + qb * 128 + tid] = srow[tid];
}

// ------ PV: normalize in place, write att, Y = P @ V (single-pass) --------
__global__ __launch_bounds__(256) void attn_pv_norm(
    float* __restrict__ att, const float* __restrict__ PS,
    const h16* __restrict__ Vth, h16* __restrict__ Yh, h16* __restrict__ Yl)
{
    const int qb = (gridDim.x - 1) - blockIdx.x;
    const int z  = blockIdx.y;
    const int b   = z >> 4;
    const int g   = (z >> 2) & 3;
    const int hkv = z & 3;

    extern __shared__ h16 sm[];
    h16 (*sPh)[72] = (h16(*)[72])sm;
    h16 (*sVh)[72] = (h16(*)[72])(sm + 128 * 72);
    float* sInv    = (float*)(sm + (128 + 64) * 72);

    const int tid  = threadIdx.x;
    const int w    = tid >> 5, lane = tid & 31;
    const int lg   = lane >> 2, tg = lane & 3;
    const int m0   = (w & 3) * 32;
    const int n0   = (w >> 2) * 32;

    if (tid < 128) {
        float s = 0.f;
        for (int k2 = 0; k2 <= qb; k2++)
            s += PS[((size_t)z * NQB + k2) * TT + qb * 128 + tid];
        sInv[tid] = 1.0f / s;
    }
    __syncthreads();

    const int prow = tid >> 1;
    const int pc   = (tid & 1) * 32;
    const int vrow = tid >> 2;
    const int vc   = (tid & 3) * 16;

    float acc[2][4][4];
#pragma unroll
    for (int i = 0; i < 2; i++)
#pragma unroll
        for (int j = 0; j < 4; j++)
#pragma unroll
            for (int v = 0; v < 4; v++) acc[i][j][v] = 0.f;

    float* attrow = att + ((size_t)z * TT + qb * 128 + prow) * TT + pc;
    const h16* vbh = Vth + (size_t)(b * KVW + hkv * 64 + vrow) * TT + vc;
    const float myinv = sInv[prow];

    const int nkb = 2 * qb + 2;

    float4 preg[8];
    uint4 vr0, vr1;
#pragma unroll
    for (int v = 0; v < 8; v++) preg[v] = *(const float4*)(attrow + v * 4);
    vr0 = *(const uint4*)(vbh);
    vr1 = *(const uint4*)(vbh + 8);

    for (int kb = 0; kb < nkb; kb++) {
#pragma unroll
        for (int v = 0; v < 8; v++) {
            float4 p = preg[v];
            __half2 t;
            t.x = __float2half_rn(p.x); t.y = __float2half_rn(p.y);
            *(__half2*)&sPh[prow][pc + v * 4] = t;
            t.x = __float2half_rn(p.z); t.y = __float2half_rn(p.w);
            *(__half2*)&sPh[prow][pc + v * 4 + 2] = t;
            float4 o;
            o.x = p.x * myinv; o.y = p.y * myinv;
            o.z = p.z * myinv; o.w = p.w * myinv;
            *(float4*)(attrow + kb * 64 + v * 4) = o;
        }
        *(uint4*)&sVh[vrow][vc]     = vr0;
        *(uint4*)&sVh[vrow][vc + 8] = vr1;
        __syncthreads();

        if (kb + 1 < nkb) {
            const float* pnext = attrow + (kb + 1) * 64;
            const h16* vnext = vbh + (kb + 1) * 64;
#pragma unroll
            for (int v = 0; v < 8; v++) preg[v] = *(const float4*)(pnext + v * 4);
            vr0 = *(const uint4*)(vnext);
            vr1 = *(const uint4*)(vnext + 8);
        }

#pragma unroll
        for (int kk = 0; kk < 64; kk += 16) {
            uint32_t ah[2][4], bh[4][2];
#pragma unroll
            for (int mt = 0; mt < 2; mt++) {
                const int r = m0 + mt * 16 + lg;
                ah[mt][0] = *(const uint32_t*)&sPh[r][kk + tg * 2];
                ah[mt][1] = *(const uint32_t*)&sPh[r + 8][kk + tg * 2];
                ah[mt][2] = *(const uint32_t*)&sPh[r][kk + tg * 2 + 8];
                ah[mt][3] = *(const uint32_t*)&sPh[r + 8][kk + tg * 2 + 8];
            }
#pragma unroll
            for (int nt = 0; nt < 4; nt++) {
                const int n = n0 + nt * 8 + lg;
                bh[nt][0] = *(const uint32_t*)&sVh[n][kk + tg * 2];
                bh[nt][1] = *(const uint32_t*)&sVh[n][kk + tg * 2 + 8];
            }
#pragma unroll
            for (int mt = 0; mt < 2; mt++)
#pragma unroll
                for (int nt = 0; nt < 4; nt++)
                    mma_f16(acc[mt][nt], ah[mt][0], ah[mt][1], ah[mt][2], ah[mt][3],
                            bh[nt][0], bh[nt][1]);
        }
        __syncthreads();
    }

    // zero-fill upper-triangle columns
    {
        const int zc0 = (qb + 1) * 128;
        const int zcols = TT - zc0;
        if (zcols > 0) {
            float4 zero = {0.f, 0.f, 0.f, 0.f};
            float* zbase = att + ((size_t)z * TT + qb * 128) * TT + zc0;
            const int c4 = zcols / 4;
            const int n4 = 128 * c4;
            for (int i = tid; i < n4; i += 256) {
                const int rr = i / c4;
                const int cc = (i - rr * c4) * 4;
                *(float4*)(zbase + (size_t)rr * TT + cc) = zero;
            }
        }
    }

    const int colbase = hkv * 256 + g * 64;
#pragma unroll
    for (int mt = 0; mt < 2; mt++) {
        const int r = m0 + mt * 16 + lg;
        const float inv0 = sInv[r];
        const float inv1 = sInv[r + 8];
#pragma unroll
        for (int nt = 0; nt < 4; nt++) {
            const int col = colbase + n0 + nt * 8 + 2 * tg;
            const int r0 = b * TT + qb * 128 + m0 + mt * 16 + lg;
            h16 h0, l0, h1, l1;
            __half2 t;
            hsplit(acc[mt][nt][0] * inv0, h0, l0); hsplit(acc[mt][nt][1] * inv0, h1, l1);
            t.x = h0; t.y = h1; *(__half2*)&Yh[(size_t)r0 * EE + col] = t;
            t.x = l0; t.y = l1; *(__half2*)&Yl[(size_t)r0 * EE + col] = t;
            hsplit(acc[mt][nt][2] * inv1, h0, l0); hsplit(acc[mt][nt][3] * inv1, h1, l1);
            t.x = h0; t.y = h1; *(__half2*)&Yh[(size_t)(r0 + 8) * EE + col] = t;
            t.x = l0; t.y = l1; *(__half2*)&Yl[(size_t)(r0 + 8) * EE + col] = t;
        }
    }
}

// ---------------- launch ----------------
extern "C" void kernel_launch(void* const* d_in, const int* in_sizes, int n_in,
                              void* d_out, int out_size)
{
    const float* x  = (const float*)d_in[0];
    const float* Wq = (const float*)d_in[2];
    const float* bq = (const float*)d_in[3];
    const float* Wk = (const float*)d_in[4];
    const float* bk = (const float*)d_in[5];
    const float* Wv = (const float*)d_in[6];
    const float* bv = (const float*)d_in[7];
    const float* Wo = (const float*)d_in[8];
    const float* bo = (const float*)d_in[9];
    float* out = (float*)d_out;

    float *Qb, *Kb, *Vb, *attScratch, *PS;
    h16 *xh, *xl, *Qh, *Kh, *Vth, *Yh, *Yl;
    h16 *Wqth, *Wkth, *Wvth, *Woth;
    cudaGetSymbolAddress((void**)&Qb, g_Q);
    cudaGetSymbolAddress((void**)&Kb, g_K);
    cudaGetSymbolAddress((void**)&Vb, g_V);
    cudaGetSymbolAddress((void**)&attScratch, g_Att);
    cudaGetSymbolAddress((void**)&PS, g_PS);
    cudaGetSymbolAddress((void**)&xh, g_xh);
    cudaGetSymbolAddress((void**)&xl, g_xl);
    cudaGetSymbolAddress((void**)&Qh, g_Qh);
    cudaGetSymbolAddress((void**)&Kh, g_Kh);
    cudaGetSymbolAddress((void**)&Vth, g_Vth);
    cudaGetSymbolAddress((void**)&Yh, g_Yh);
    cudaGetSymbolAddress((void**)&Yl, g_Yl);
    cudaGetSymbolAddress((void**)&Wqth, g_Wqth);
    cudaGetSymbolAddress((void**)&Wkth, g_Wkth);
    cudaGetSymbolAddress((void**)&Wvth, g_Wvth);
    cudaGetSymbolAddress((void**)&Woth, g_Woth);

    float* att = ((size_t)out_size >= Y_ELEMS + ATT_ELEMS) ? (out + Y_ELEMS)
                                                           : attScratch;

    const int SMEM_GEMM = 3 * NSTAGE * 128 * PITCH * (int)sizeof(h16);   // 122880
    const int SMEM_SC = 2 * 128 * 72 * (int)sizeof(h16);                 // 36864
    const int SMEM_PV = (128 + 64) * 72 * (int)sizeof(h16) + 512;        // 28160
    cudaFuncSetAttribute(gemm2p,     cudaFuncAttributeMaxDynamicSharedMemorySize, SMEM_GEMM);
    cudaFuncSetAttribute(gemm2p_qkv, cudaFuncAttributeMaxDynamicSharedMemorySize, SMEM_GEMM);
    cudaFuncSetAttribute(attn_scores_exp, cudaFuncAttributeMaxDynamicSharedMemorySize, SMEM_SC);
    cudaFuncSetAttribute(attn_pv_norm,   cudaFuncAttributeMaxDynamicSharedMemorySize, SMEM_PV);

    // 0) preprocessing
    wtrans_all<<<dim3(32, 32, 4), dim3(32, 8)>>>(Wq, Wk, Wv, Wo, Wqth, Wkth, Wvth, Woth);
    split_x<<<(ROWS * EE / 4 + 255) / 256, 256>>>((const float4*)x, xh, xl, ROWS * EE / 4);

    // 1) fused QKV projections (4-stage pipeline)
    gemm2p_qkv<<<dim3(8, ROWS / 128, 2), 256, SMEM_GEMM>>>(
        xh, xl, Wqth, bq, Qb, Wkth, bk, Kb, Wvth, bv, Vb);

    // 2) RoPE (hi only); V transpose+convert
    rope_half<<<(ROWS * HQn * 32) / 256, 256>>>(Qb, Qh, HQn);
    rope_half<<<(ROWS * HKVn * 32) / 256, 256>>>(Kb, Kh, HKVn);
    vtrans_half<<<dim3(KVW / 32, ROWS / 32), dim3(32, 8)>>>(Vb, Vth);

    // 3) scores + exp + partial sums (single-pass fp16)
    attn_scores_exp<<<dim3(NQB * (NQB + 1) / 2, ZHEADS), 256, SMEM_SC>>>(
        Qh, Kh, att, PS);

    // 4) PV: normalize in place + write att + Y (single-pass fp16)
    attn_pv_norm<<<dim3(NQB, ZHEADS), 256, SMEM_PV>>>(att, PS, Vth, Yh, Yl);

    // 5) output projection (2-pass, 4-stage pipeline)
    gemm2p<<<dim3(EE / 128, ROWS / 128), 256, SMEM_GEMM>>>(Yh, Yl, Woth, bo, out, EE, EE);
}

// round 16
// speedup vs baseline: 1.1079x; 1.1079x over previous
#include <cuda_runtime.h>
#include <cuda_fp16.h>
#include <math.h>
#include <stdint.h>

#define BB   2
#define TT   2048
#define EE   1024
#define HQn  16
#define HKVn 4
#define DD   64
#define GG   4

#define ROWS (BB*TT)
#define KVW  (HKVn*DD)
#define Y_ELEMS  ((size_t)BB*TT*EE)
#define ATT_ELEMS ((size_t)BB*HQn*TT*TT)
#define ZHEADS (BB*HQn)
#define NQB    (TT/128)

typedef __half h16;

// ---------------- device scratch ----------------
__device__ float g_Q[ROWS * EE];
__device__ float g_K[ROWS * KVW];
__device__ float g_V[ROWS * KVW];
__device__ float g_Att[ATT_ELEMS];
__device__ float g_PS[ZHEADS * NQB * TT];

__device__ h16 g_xh[ROWS * EE];
__device__ h16 g_Qh[ROWS * EE];
__device__ h16 g_Kh[ROWS * KVW];
__device__ h16 g_Vth[BB * KVW * TT];
__device__ h16 g_Yh[ROWS * EE],  g_Yl[ROWS * EE];
__device__ h16 g_Wqth[EE * EE];
__device__ h16 g_Wkth[EE * KVW];
__device__ h16 g_Wvth[EE * KVW];
__device__ h16 g_Woth[EE * EE];

// ---------------- helpers ----------------
__device__ __forceinline__ void hsplit(float x, h16& h, h16& l)
{
    h = __float2half_rn(x);
    l = __float2half_rn(x - __half2float(h));
}

__device__ __forceinline__ void mma_f16(float (&c)[4],
                                        uint32_t a0, uint32_t a1,
                                        uint32_t a2, uint32_t a3,
                                        uint32_t b0, uint32_t b1)
{
    asm volatile(
        "mma.sync.aligned.m16n8k16.row.col.f32.f16.f16.f32 "
        "{%0,%1,%2,%3}, {%4,%5,%6,%7}, {%8,%9}, {%0,%1,%2,%3};"
        : "+f"(c[0]), "+f"(c[1]), "+f"(c[2]), "+f"(c[3])
        : "r"(a0), "r"(a1), "r"(a2), "r"(a3), "r"(b0), "r"(b1));
}

__device__ __forceinline__ uint32_t smem_u32(const void* p)
{
    return (uint32_t)__cvta_generic_to_shared(p);
}

__device__ __forceinline__ void cp16(uint32_t dst, const void* src)
{
    asm volatile("cp.async.cg.shared.global [%0], [%1], 16;" :: "r"(dst), "l"(src));
}
#define CP_COMMIT() asm volatile("cp.async.commit_group;")
#define CP_WAIT1()  asm volatile("cp.async.wait_group 1;")

__device__ __forceinline__ void ldsm_x4(uint32_t& r0, uint32_t& r1,
                                        uint32_t& r2, uint32_t& r3, uint32_t a)
{
    asm volatile("ldmatrix.sync.aligned.m8n8.x4.shared.b16 {%0,%1,%2,%3}, [%4];"
        : "=r"(r0), "=r"(r1), "=r"(r2), "=r"(r3) : "r"(a));
}

// ---------------- preprocessing ----------------
__global__ __launch_bounds__(256) void wtrans_all(
    const float* __restrict__ Wq, const float* __restrict__ Wk,
    const float* __restrict__ Wv, const float* __restrict__ Wo,
    h16* __restrict__ Dq, h16* __restrict__ Dk,
    h16* __restrict__ Dv, h16* __restrict__ Do)
{
    const int z = blockIdx.z;
    const float* W; h16* D; int N;
    if      (z == 0) { W = Wq; D = Dq; N = EE;  }
    else if (z == 1) { W = Wk; D = Dk; N = KVW; }
    else if (z == 2) { W = Wv; D = Dv; N = KVW; }
    else             { W = Wo; D = Do; N = EE;  }
    const int c0 = blockIdx.x * 32;
    if (c0 >= N) return;
    const int r0 = blockIdx.y * 32;

    __shared__ float s[32][33];
    const int tx = threadIdx.x, ty = threadIdx.y;
    for (int i = ty; i < 32; i += 8)
        s[i][tx] = W[(size_t)(r0 + i) * N + c0 + tx];
    __syncthreads();
    for (int i = ty; i < 32; i += 8)
        D[(size_t)(c0 + i) * EE + r0 + tx] = __float2half_rn(s[tx][i]);
}

__global__ __launch_bounds__(256) void vtrans_half(
    const float* __restrict__ V, h16* __restrict__ Vth)
{
    __shared__ float s[32][33];
    const int c0 = blockIdx.x * 32;
    const int r0 = blockIdx.y * 32;
    const int b  = r0 >> 11;
    const int t0 = r0 & 2047;
    const int tx = threadIdx.x, ty = threadIdx.y;
    for (int i = ty; i < 32; i += 8)
        s[i][tx] = V[(size_t)(r0 + i) * KVW + c0 + tx];
    __syncthreads();
    for (int i = ty; i < 32; i += 8)
        Vth[(size_t)(b * KVW + c0 + i) * TT + t0 + tx] = __float2half_rn(s[tx][i]);
}

// x fp32 -> fp16 (hi only)
__global__ __launch_bounds__(256) void conv_x(
    const float4* __restrict__ src, h16* __restrict__ hi, int n4)
{
    int i = blockIdx.x * 256 + threadIdx.x;
    if (i >= n4) return;
    float4 v = src[i];
    __half2 a, b2;
    a.x = __float2half_rn(v.x); a.y = __float2half_rn(v.y);
    b2.x = __float2half_rn(v.z); b2.y = __float2half_rn(v.w);
    ((__half2*)hi)[2 * i] = a; ((__half2*)hi)[2 * i + 1] = b2;
}

// Y fp(acc) already split in PV epilogue -> nothing needed here.

// -------- GEMM single-pass fp16: 2-stage cp.async + ldmatrix --------------
#define BKG   32
#define PITCH 40

__device__ __forceinline__ void gemm1p_body(
    const h16* __restrict__ Ah, const h16* __restrict__ Bth,
    const float* __restrict__ bias, float* __restrict__ C,
    int blkM, int blkN, int N, int K)
{
    extern __shared__ h16 smp[];
    h16* sAh = smp;
    h16* sBh = smp + 2 * 128 * PITCH;
    const uint32_t stStride = 128 * PITCH * 2;

    const int tid  = threadIdx.x;
    const int w    = tid >> 5, lane = tid & 31;
    const int m0   = (w & 1) * 64;
    const int n0   = (w >> 1) * 32;

    const int lr = tid >> 2;
    const int lk = (tid & 3) * 8;
    const h16* gAh = Ah  + (size_t)(blkM + lr) * K + lk;
    const h16* gB  = Bth + (size_t)(blkN + lr) * K + lk;

    const uint32_t dAh0 = smem_u32(sAh) + (lr * PITCH + lk) * 2;
    const uint32_t dAh1 = smem_u32(sAh) + ((lr + 64) * PITCH + lk) * 2;
    const uint32_t dB0  = smem_u32(sBh) + (lr * PITCH + lk) * 2;
    const uint32_t dB1  = smem_u32(sBh) + ((lr + 64) * PITCH + lk) * 2;

    const uint32_t offA = ((lane & 15) * PITCH + (lane >> 4) * 8) * 2;
    const uint32_t offB = ((((lane >> 4) * 8) + (lane & 7)) * PITCH + ((lane >> 3) & 1) * 8) * 2;
    const uint32_t aAh = smem_u32(sAh) + offA;
    const uint32_t aB  = smem_u32(sBh) + offB;

    float acc[4][4][4];
#pragma unroll
    for (int i = 0; i < 4; i++)
#pragma unroll
        for (int j = 0; j < 4; j++)
#pragma unroll
            for (int v = 0; v < 4; v++) acc[i][j][v] = 0.f;

    const int niter = K / BKG;

    {
        cp16(dAh0, gAh); cp16(dAh1, gAh + (size_t)64 * K);
        cp16(dB0,  gB);  cp16(dB1,  gB  + (size_t)64 * K);
        CP_COMMIT();
    }

    for (int it = 0; it < niter; it++) {
        if (it + 1 < niter) {
            const int st = (it + 1) & 1;
            const int k0 = (it + 1) * BKG;
            const uint32_t so = st * stStride;
            cp16(dAh0 + so, gAh + k0); cp16(dAh1 + so, gAh + (size_t)64 * K + k0);
            cp16(dB0 + so,  gB + k0);  cp16(dB1 + so,  gB  + (size_t)64 * K + k0);
        }
        CP_COMMIT();
        CP_WAIT1();
        __syncthreads();

        const uint32_t so = (it & 1) * stStride;
#pragma unroll
        for (int kk = 0; kk < BKG; kk += 16) {
            uint32_t ah[4][4], bh[4][2];
#pragma unroll
            for (int mt = 0; mt < 4; mt++) {
                const uint32_t rowoff = ((m0 + mt * 16) * PITCH + kk) * 2;
                ldsm_x4(ah[mt][0], ah[mt][1], ah[mt][2], ah[mt][3], aAh + so + rowoff);
            }
            ldsm_x4(bh[0][0], bh[0][1], bh[1][0], bh[1][1],
                    aB + so + ((n0)      * PITCH + kk) * 2);
            ldsm_x4(bh[2][0], bh[2][1], bh[3][0], bh[3][1],
                    aB + so + ((n0 + 16) * PITCH + kk) * 2);
#pragma unroll
            for (int mt = 0; mt < 4; mt++)
#pragma unroll
                for (int nt = 0; nt < 4; nt++)
                    mma_f16(acc[mt][nt], ah[mt][0], ah[mt][1], ah[mt][2], ah[mt][3],
                            bh[nt][0], bh[nt][1]);
        }
        __syncthreads();
    }

    const int lg = lane >> 2, tg = lane & 3;
#pragma unroll
    for (int mt = 0; mt < 4; mt++)
#pragma unroll
        for (int nt = 0; nt < 4; nt++) {
            const int col = blkN + n0 + nt * 8 + 2 * tg;
            const float b0 = bias[col], b1 = bias[col + 1];
            const int r0 = blkM + m0 + mt * 16 + lg;
            float2 o;
            o.x = acc[mt][nt][0] + b0; o.y = acc[mt][nt][1] + b1;
            *(float2*)(C + (size_t)r0 * N + col) = o;
            o.x = acc[mt][nt][2] + b0; o.y = acc[mt][nt][3] + b1;
            *(float2*)(C + (size_t)(r0 + 8) * N + col) = o;
        }
}

__global__ __launch_bounds__(256) void gemm1p_qkv(
    const h16* __restrict__ xh,
    const h16* __restrict__ Wqth, const float* __restrict__ bq, float* __restrict__ Qout,
    const h16* __restrict__ Wkth, const float* __restrict__ bk, float* __restrict__ Kout,
    const h16* __restrict__ Wvth, const float* __restrict__ bv, float* __restrict__ Vout)
{
    const int blkM = blockIdx.y * 128;
    if (blockIdx.z == 0) {
        gemm1p_body(xh, Wqth, bq, Qout, blkM, blockIdx.x * 128, EE, EE);
    } else {
        const int x = blockIdx.x;
        if (x < 2)      gemm1p_body(xh, Wkth, bk, Kout, blkM, x * 128, KVW, EE);
        else if (x < 4) gemm1p_body(xh, Wvth, bv, Vout, blkM, (x - 2) * 128, KVW, EE);
    }
}

// -------- GEMM 2-pass fp16 (O-projection): 2-stage cp.async + ldmatrix ----
__global__ __launch_bounds__(256) void gemm2p(
    const h16* __restrict__ Ah, const h16* __restrict__ Al,
    const h16* __restrict__ Bth, const float* __restrict__ bias,
    float* __restrict__ C, int N, int K)
{
    extern __shared__ h16 smp[];
    h16* sAh = smp;
    h16* sAl = smp + 2 * 128 * PITCH;
    h16* sBh = smp + 4 * 128 * PITCH;
    const uint32_t stStride = 128 * PITCH * 2;

    const int blkM = blockIdx.y * 128;
    const int blkN = blockIdx.x * 128;

    const int tid  = threadIdx.x;
    const int w    = tid >> 5, lane = tid & 31;
    const int m0   = (w & 1) * 64;
    const int n0   = (w >> 1) * 32;

    const int lr = tid >> 2;
    const int lk = (tid & 3) * 8;
    const h16* gAh = Ah  + (size_t)(blkM + lr) * K + lk;
    const h16* gAl = Al  + (size_t)(blkM + lr) * K + lk;
    const h16* gB  = Bth + (size_t)(blkN + lr) * K + lk;

    const uint32_t dAh0 = smem_u32(sAh) + (lr * PITCH + lk) * 2;
    const uint32_t dAh1 = smem_u32(sAh) + ((lr + 64) * PITCH + lk) * 2;
    const uint32_t dAl0 = smem_u32(sAl) + (lr * PITCH + lk) * 2;
    const uint32_t dAl1 = smem_u32(sAl) + ((lr + 64) * PITCH + lk) * 2;
    const uint32_t dB0  = smem_u32(sBh) + (lr * PITCH + lk) * 2;
    const uint32_t dB1  = smem_u32(sBh) + ((lr + 64) * PITCH + lk) * 2;

    const uint32_t offA = ((lane & 15) * PITCH + (lane >> 4) * 8) * 2;
    const uint32_t offB = ((((lane >> 4) * 8) + (lane & 7)) * PITCH + ((lane >> 3) & 1) * 8) * 2;
    const uint32_t aAh = smem_u32(sAh) + offA;
    const uint32_t aAl = smem_u32(sAl) + offA;
    const uint32_t aB  = smem_u32(sBh) + offB;

    float acc[4][4][4];
#pragma unroll
    for (int i = 0; i < 4; i++)
#pragma unroll
        for (int j = 0; j < 4; j++)
#pragma unroll
            for (int v = 0; v < 4; v++) acc[i][j][v] = 0.f;

    const int niter = K / BKG;

    {
        cp16(dAh0, gAh); cp16(dAh1, gAh + (size_t)64 * K);
        cp16(dAl0, gAl); cp16(dAl1, gAl + (size_t)64 * K);
        cp16(dB0,  gB);  cp16(dB1,  gB  + (size_t)64 * K);
        CP_COMMIT();
    }

    for (int it = 0; it < niter; it++) {
        if (it + 1 < niter) {
            const int st = (it + 1) & 1;
            const int k0 = (it + 1) * BKG;
            const uint32_t so = st * stStride;
            cp16(dAh0 + so, gAh + k0); cp16(dAh1 + so, gAh + (size_t)64 * K + k0);
            cp16(dAl0 + so, gAl + k0); cp16(dAl1 + so, gAl + (size_t)64 * K + k0);
            cp16(dB0 + so,  gB + k0);  cp16(dB1 + so,  gB  + (size_t)64 * K + k0);
        }
        CP_COMMIT();
        CP_WAIT1();
        __syncthreads();

        const uint32_t so = (it & 1) * stStride;
#pragma unroll
        for (int kk = 0; kk < BKG; kk += 16) {
            uint32_t ah[4][4], al[4][4], bh[4][2];
#pragma unroll
            for (int mt = 0; mt < 4; mt++) {
                const uint32_t rowoff = ((m0 + mt * 16) * PITCH + kk) * 2;
                ldsm_x4(ah[mt][0], ah[mt][1], ah[mt][2], ah[mt][3], aAh + so + rowoff);
                ldsm_x4(al[mt][0], al[mt][1], al[mt][2], al[mt][3], aAl + so + rowoff);
            }
            ldsm_x4(bh[0][0], bh[0][1], bh[1][0], bh[1][1],
                    aB + so + ((n0)      * PITCH + kk) * 2);
            ldsm_x4(bh[2][0], bh[2][1], bh[3][0], bh[3][1],
                    aB + so + ((n0 + 16) * PITCH + kk) * 2);
#pragma unroll
            for (int mt = 0; mt < 4; mt++)
#pragma unroll
                for (int nt = 0; nt < 4; nt++) {
                    mma_f16(acc[mt][nt], ah[mt][0], ah[mt][1], ah[mt][2], ah[mt][3],
                            bh[nt][0], bh[nt][1]);
                    mma_f16(acc[mt][nt], al[mt][0], al[mt][1], al[mt][2], al[mt][3],
                            bh[nt][0], bh[nt][1]);
                }
        }
        __syncthreads();
    }

    const int lg = lane >> 2, tg = lane & 3;
#pragma unroll
    for (int mt = 0; mt < 4; mt++)
#pragma unroll
        for (int nt = 0; nt < 4; nt++) {
            const int col = blkN + n0 + nt * 8 + 2 * tg;
            const float b0 = bias[col], b1 = bias[col + 1];
            const int r0 = blkM + m0 + mt * 16 + lg;
            float2 o;
            o.x = acc[mt][nt][0] + b0; o.y = acc[mt][nt][1] + b1;
            *(float2*)(C + (size_t)r0 * N + col) = o;
            o.x = acc[mt][nt][2] + b0; o.y = acc[mt][nt][3] + b1;
            *(float2*)(C + (size_t)(r0 + 8) * N + col) = o;
        }
}

// ---------------- RoPE (hi only) ----------------
__global__ __launch_bounds__(256) void rope_half(
    const float* __restrict__ buf, h16* __restrict__ hi, int nheads)
{
    int idx = blockIdx.x * 256 + threadIdx.x;
    int ii  = idx & 31;
    int h   = (idx >> 5) % nheads;
    int row = idx / (32 * nheads);
    int t   = row & (TT - 1);
    float ang = (float)(t + 1) * exp2f((float)ii * (-13.2877123795494f / 32.0f));
    float sn, cs;
    sincosf(ang, &sn, &cs);
    size_t off = (size_t)row * (nheads * 64) + h * 64 + ii;
    float x0 = buf[off], x1 = buf[off + 32];
    hi[off]      = __float2half_rn(x0 * cs - x1 * sn);
    hi[off + 32] = __float2half_rn(x1 * cs + x0 * sn);
}

// -------- scores: P~ = exp(Qh·Kh^T/8), single-pass fp16 -------------------
__global__ __launch_bounds__(256) void attn_scores_exp(
    const h16* __restrict__ Qh, const h16* __restrict__ Kh,
    float* __restrict__ att, float* __restrict__ PS)
{
    int idx = blockIdx.x;
    int qb = (int)((sqrtf(8.f * idx + 1.f) - 1.f) * 0.5f);
    while ((qb + 1) * (qb + 2) / 2 <= idx) qb++;
    while (qb * (qb + 1) / 2 > idx) qb--;
    const int kb = idx - qb * (qb + 1) / 2;

    const int z   = blockIdx.y;
    const int b   = z >> 4;
    const int g   = (z >> 2) & 3;
    const int hkv = z & 3;
    const int hq  = hkv * GG + g;

    extern __shared__ h16 sm[];
    h16 (*sQh)[72] = (h16(*)[72])sm;
    h16 (*sKh)[72] = (h16(*)[72])(sm + 128 * 72);

    const int tid  = threadIdx.x;
    const int w    = tid >> 5, lane = tid & 31;
    const int lg   = lane >> 2, tg = lane & 3;
    const int m0   = (w & 1) * 64;
    const int n0   = (w >> 1) * 32;

    {
        const int lrow = tid >> 1;
        const int lc   = (tid & 1) * 32;
        const h16* qh = Qh + (size_t)(b * TT + qb * 128 + lrow) * EE + hq * 64 + lc;
        const h16* kh = Kh + (size_t)(b * TT + kb * 128 + lrow) * KVW + hkv * 64 + lc;
#pragma unroll
        for (int v = 0; v < 4; v++) {
            *(uint4*)&sQh[lrow][lc + v * 8] = *(const uint4*)(qh + v * 8);
            *(uint4*)&sKh[lrow][lc + v * 8] = *(const uint4*)(kh + v * 8);
        }
    }
    __syncthreads();

    float acc[4][4][4];
#pragma unroll
    for (int i = 0; i < 4; i++)
#pragma unroll
        for (int j = 0; j < 4; j++)
#pragma unroll
            for (int v = 0; v < 4; v++) acc[i][j][v] = 0.f;

#pragma unroll
    for (int kk = 0; kk < 64; kk += 16) {
        uint32_t ah[4][4], bh[4][2];
#pragma unroll
        for (int mt = 0; mt < 4; mt++) {
            const int r = m0 + mt * 16 + lg;
            ah[mt][0] = *(const uint32_t*)&sQh[r][kk + tg * 2];
            ah[mt][1] = *(const uint32_t*)&sQh[r + 8][kk + tg * 2];
            ah[mt][2] = *(const uint32_t*)&sQh[r][kk + tg * 2 + 8];
            ah[mt][3] = *(const uint32_t*)&sQh[r + 8][kk + tg * 2 + 8];
        }
#pragma unroll
        for (int nt = 0; nt < 4; nt++) {
            const int n = n0 + nt * 8 + lg;
            bh[nt][0] = *(const uint32_t*)&sKh[n][kk + tg * 2];
            bh[nt][1] = *(const uint32_t*)&sKh[n][kk + tg * 2 + 8];
        }
#pragma unroll
        for (int mt = 0; mt < 4; mt++)
#pragma unroll
            for (int nt = 0; nt < 4; nt++)
                mma_f16(acc[mt][nt], ah[mt][0], ah[mt][1], ah[mt][2], ah[mt][3],
                        bh[nt][0], bh[nt][1]);
    }

    __syncthreads();
    float* srow = (float*)sm;
    if (tid < 128) srow[tid] = 0.f;
    __syncthreads();

    float* obase = att + ((size_t)z * TT + qb * 128) * TT + kb * 128;
    const bool diag = (kb == qb);

#pragma unroll
    for (int mt = 0; mt < 4; mt++) {
        const int r0 = m0 + mt * 16 + lg;
        float s0 = 0.f, s1 = 0.f;
#pragma unroll
        for (int nt = 0; nt < 4; nt++) {
            const int col = n0 + nt * 8 + 2 * tg;
            float p0 = __expf(acc[mt][nt][0] * 0.125f);
            float p1 = __expf(acc[mt][nt][1] * 0.125f);
            float p2 = __expf(acc[mt][nt][2] * 0.125f);
            float p3 = __expf(acc[mt][nt][3] * 0.125f);
            if (diag) {
                if (col > r0)         p0 = 0.f;
                if (col + 1 > r0)     p1 = 0.f;
                if (col > r0 + 8)     p2 = 0.f;
                if (col + 1 > r0 + 8) p3 = 0.f;
            }
            s0 += p0 + p1;
            s1 += p2 + p3;
            float2 o;
            o.x = p0; o.y = p1;
            *(float2*)(obase + (size_t)r0 * TT + col) = o;
            o.x = p2; o.y = p3;
            *(float2*)(obase + (size_t)(r0 + 8) * TT + col) = o;
        }
        s0 += __shfl_xor_sync(0xffffffffu, s0, 1);
        s0 += __shfl_xor_sync(0xffffffffu, s0, 2);
        s1 += __shfl_xor_sync(0xffffffffu, s1, 1);
        s1 += __shfl_xor_sync(0xffffffffu, s1, 2);
        if (tg == 0) {
            atomicAdd(&srow[r0], s0);
            atomicAdd(&srow[r0 + 8], s1);
        }
    }
    __syncthreads();
    if (tid < 128)
        PS[((size_t)z * NQB + kb) * TT + qb * 128 + tid] = srow[tid];
}

// ------ PV: normalize in place, write att, Y = P @ V (single-pass) --------
__global__ __launch_bounds__(256) void attn_pv_norm(
    float* __restrict__ att, const float* __restrict__ PS,
    const h16* __restrict__ Vth, h16* __restrict__ Yh, h16* __restrict__ Yl)
{
    const int qb = (gridDim.x - 1) - blockIdx.x;
    const int z  = blockIdx.y;
    const int b   = z >> 4;
    const int g   = (z >> 2) & 3;
    const int hkv = z & 3;

    extern __shared__ h16 sm[];
    h16 (*sPh)[72] = (h16(*)[72])sm;
    h16 (*sVh)[72] = (h16(*)[72])(sm + 128 * 72);
    float* sInv    = (float*)(sm + (128 + 64) * 72);

    const int tid  = threadIdx.x;
    const int w    = tid >> 5, lane = tid & 31;
    const int lg   = lane >> 2, tg = lane & 3;
    const int m0   = (w & 3) * 32;
    const int n0   = (w >> 2) * 32;

    if (tid < 128) {
        float s = 0.f;
        for (int k2 = 0; k2 <= qb; k2++)
            s += PS[((size_t)z * NQB + k2) * TT + qb * 128 + tid];
        sInv[tid] = 1.0f / s;
    }
    __syncthreads();

    const int prow = tid >> 1;
    const int pc   = (tid & 1) * 32;
    const int vrow = tid >> 2;
    const int vc   = (tid & 3) * 16;

    float acc[2][4][4];
#pragma unroll
    for (int i = 0; i < 2; i++)
#pragma unroll
        for (int j = 0; j < 4; j++)
#pragma unroll
            for (int v = 0; v < 4; v++) acc[i][j][v] = 0.f;

    float* attrow = att + ((size_t)z * TT + qb * 128 + prow) * TT + pc;
    const h16* vbh = Vth + (size_t)(b * KVW + hkv * 64 + vrow) * TT + vc;
    const float myinv = sInv[prow];

    const int nkb = 2 * qb + 2;

    float4 preg[8];
    uint4 vr0, vr1;
#pragma unroll
    for (int v = 0; v < 8; v++) preg[v] = *(const float4*)(attrow + v * 4);
    vr0 = *(const uint4*)(vbh);
    vr1 = *(const uint4*)(vbh + 8);

    for (int kb = 0; kb < nkb; kb++) {
#pragma unroll
        for (int v = 0; v < 8; v++) {
            float4 p = preg[v];
            __half2 t;
            t.x = __float2half_rn(p.x); t.y = __float2half_rn(p.y);
            *(__half2*)&sPh[prow][pc + v * 4] = t;
            t.x = __float2half_rn(p.z); t.y = __float2half_rn(p.w);
            *(__half2*)&sPh[prow][pc + v * 4 + 2] = t;
            float4 o;
            o.x = p.x * myinv; o.y = p.y * myinv;
            o.z = p.z * myinv; o.w = p.w * myinv;
            *(float4*)(attrow + kb * 64 + v * 4) = o;
        }
        *(uint4*)&sVh[vrow][vc]     = vr0;
        *(uint4*)&sVh[vrow][vc + 8] = vr1;
        __syncthreads();

        if (kb + 1 < nkb) {
            const float* pnext = attrow + (kb + 1) * 64;
            const h16* vnext = vbh + (kb + 1) * 64;
#pragma unroll
            for (int v = 0; v < 8; v++) preg[v] = *(const float4*)(pnext + v * 4);
            vr0 = *(const uint4*)(vnext);
            vr1 = *(const uint4*)(vnext + 8);
        }

#pragma unroll
        for (int kk = 0; kk < 64; kk += 16) {
            uint32_t ah[2][4], bh[4][2];
#pragma unroll
            for (int mt = 0; mt < 2; mt++) {
                const int r = m0 + mt * 16 + lg;
                ah[mt][0] = *(const uint32_t*)&sPh[r][kk + tg * 2];
                ah[mt][1] = *(const uint32_t*)&sPh[r + 8][kk + tg * 2];
                ah[mt][2] = *(const uint32_t*)&sPh[r][kk + tg * 2 + 8];
                ah[mt][3] = *(const uint32_t*)&sPh[r + 8][kk + tg * 2 + 8];
            }
#pragma unroll
            for (int nt = 0; nt < 4; nt++) {
                const int n = n0 + nt * 8 + lg;
                bh[nt][0] = *(const uint32_t*)&sVh[n][kk + tg * 2];
                bh[nt][1] = *(const uint32_t*)&sVh[n][kk + tg * 2 + 8];
            }
#pragma unroll
            for (int mt = 0; mt < 2; mt++)
#pragma unroll
                for (int nt = 0; nt < 4; nt++)
                    mma_f16(acc[mt][nt], ah[mt][0], ah[mt][1], ah[mt][2], ah[mt][3],
                            bh[nt][0], bh[nt][1]);
        }
        __syncthreads();
    }

    // zero-fill upper-triangle columns
    {
        const int zc0 = (qb + 1) * 128;
        const int zcols = TT - zc0;
        if (zcols > 0) {
            float4 zero = {0.f, 0.f, 0.f, 0.f};
            float* zbase = att + ((size_t)z * TT + qb * 128) * TT + zc0;
            const int c4 = zcols / 4;
            const int n4 = 128 * c4;
            for (int i = tid; i < n4; i += 256) {
                const int rr = i / c4;
                const int cc = (i - rr * c4) * 4;
                *(float4*)(zbase + (size_t)rr * TT + cc) = zero;
            }
        }
    }

    const int colbase = hkv * 256 + g * 64;
#pragma unroll
    for (int mt = 0; mt < 2; mt++) {
        const int r = m0 + mt * 16 + lg;
        const float inv0 = sInv[r];
        const float inv1 = sInv[r + 8];
#pragma unroll
        for (int nt = 0; nt < 4; nt++) {
            const int col = colbase + n0 + nt * 8 + 2 * tg;
            const int r0 = b * TT + qb * 128 + m0 + mt * 16 + lg;
            h16 h0, l0, h1, l1;
            __half2 t;
            hsplit(acc[mt][nt][0] * inv0, h0, l0); hsplit(acc[mt][nt][1] * inv0, h1, l1);
            t.x = h0; t.y = h1; *(__half2*)&Yh[(size_t)r0 * EE + col] = t;
            t.x = l0; t.y = l1; *(__half2*)&Yl[(size_t)r0 * EE + col] = t;
            hsplit(acc[mt][nt][2] * inv1, h0, l0); hsplit(acc[mt][nt][3] * inv1, h1, l1);
            t.x = h0; t.y = h1; *(__half2*)&Yh[(size_t)(r0 + 8) * EE + col] = t;
            t.x = l0; t.y = l1; *(__half2*)&Yl[(size_t)(r0 + 8) * EE + col] = t;
        }
    }
}

// ---------------- launch ----------------
extern "C" void kernel_launch(void* const* d_in, const int* in_sizes, int n_in,
                              void* d_out, int out_size)
{
    const float* x  = (const float*)d_in[0];
    const float* Wq = (const float*)d_in[2];
    const float* bq = (const float*)d_in[3];
    const float* Wk = (const float*)d_in[4];
    const float* bk = (const float*)d_in[5];
    const float* Wv = (const float*)d_in[6];
    const float* bv = (const float*)d_in[7];
    const float* Wo = (const float*)d_in[8];
    const float* bo = (const float*)d_in[9];
    float* out = (float*)d_out;

    float *Qb, *Kb, *Vb, *attScratch, *PS;
    h16 *xh, *Qh, *Kh, *Vth, *Yh, *Yl;
    h16 *Wqth, *Wkth, *Wvth, *Woth;
    cudaGetSymbolAddress((void**)&Qb, g_Q);
    cudaGetSymbolAddress((void**)&Kb, g_K);
    cudaGetSymbolAddress((void**)&Vb, g_V);
    cudaGetSymbolAddress((void**)&attScratch, g_Att);
    cudaGetSymbolAddress((void**)&PS, g_PS);
    cudaGetSymbolAddress((void**)&xh, g_xh);
    cudaGetSymbolAddress((void**)&Qh, g_Qh);
    cudaGetSymbolAddress((void**)&Kh, g_Kh);
    cudaGetSymbolAddress((void**)&Vth, g_Vth);
    cudaGetSymbolAddress((void**)&Yh, g_Yh);
    cudaGetSymbolAddress((void**)&Yl, g_Yl);
    cudaGetSymbolAddress((void**)&Wqth, g_Wqth);
    cudaGetSymbolAddress((void**)&Wkth, g_Wkth);
    cudaGetSymbolAddress((void**)&Wvth, g_Wvth);
    cudaGetSymbolAddress((void**)&Woth, g_Woth);

    float* att = ((size_t)out_size >= Y_ELEMS + ATT_ELEMS) ? (out + Y_ELEMS)
                                                           : attScratch;

    const int SMEM_G1 = 4 * 128 * PITCH * (int)sizeof(h16);              // 40960
    const int SMEM_G2 = 6 * 128 * PITCH * (int)sizeof(h16);              // 61440
    const int SMEM_SC = 2 * 128 * 72 * (int)sizeof(h16);                 // 36864
    const int SMEM_PV = (128 + 64) * 72 * (int)sizeof(h16) + 512;        // 28160
    cudaFuncSetAttribute(gemm1p_qkv, cudaFuncAttributeMaxDynamicSharedMemorySize, SMEM_G1);
    cudaFuncSetAttribute(gemm2p,     cudaFuncAttributeMaxDynamicSharedMemorySize, SMEM_G2);
    cudaFuncSetAttribute(attn_scores_exp, cudaFuncAttributeMaxDynamicSharedMemorySize, SMEM_SC);
    cudaFuncSetAttribute(attn_pv_norm,   cudaFuncAttributeMaxDynamicSharedMemorySize, SMEM_PV);

    // 0) preprocessing
    wtrans_all<<<dim3(32, 32, 4), dim3(32, 8)>>>(Wq, Wk, Wv, Wo, Wqth, Wkth, Wvth, Woth);
    conv_x<<<(ROWS * EE / 4 + 255) / 256, 256>>>((const float4*)x, xh, ROWS * EE / 4);

    // 1) fused QKV projections (single-pass fp16, 2-stage pipeline)
    gemm1p_qkv<<<dim3(8, ROWS / 128, 2), 256, SMEM_G1>>>(
        xh, Wqth, bq, Qb, Wkth, bk, Kb, Wvth, bv, Vb);

    // 2) RoPE (hi only); V transpose+convert
    rope_half<<<(ROWS * HQn * 32) / 256, 256>>>(Qb, Qh, HQn);
    rope_half<<<(ROWS * HKVn * 32) / 256, 256>>>(Kb, Kh, HKVn);
    vtrans_half<<<dim3(KVW / 32, ROWS / 32), dim3(32, 8)>>>(Vb, Vth);

    // 3) scores + exp + partial sums (single-pass fp16)
    attn_scores_exp<<<dim3(NQB * (NQB + 1) / 2, ZHEADS), 256, SMEM_SC>>>(
        Qh, Kh, att, PS);

    // 4) PV: normalize in place + write att + Y (single-pass fp16)
    attn_pv_norm<<<dim3(NQB, ZHEADS), 256, SMEM_PV>>>(att, PS, Vth, Yh, Yl);

    // 5) output projection (2-pass, 2-stage pipeline — protects y accuracy)
    gemm2p<<<dim3(EE / 128, ROWS / 128), 256, SMEM_G2>>>(Yh, Yl, Woth, bo, out, EE, EE);
}